// round 14
// baseline (speedup 1.0000x reference)
#include <cuda_runtime.h>
#include <cstdint>
#include <math.h>

#define NODE_DIM_   128
#define NUM_IRREPS_ 224
#define SPH_DIM_    480
#define HIDDEN_     576
#define NUM_BASIS_  20
#define N_NODES_    30000
#define N_EDGES_    480000
#define SORT_BLKS_  148

// Scratch (device globals)
__device__ float g_hidden[(size_t)N_NODES_ * NODE_DIM_];
__device__ float g_scalar_out[(size_t)N_NODES_ * HIDDEN_];
__device__ int   g_count[N_NODES_];
__device__ int   g_offs[N_NODES_ + 1];
__device__ int   g_cursor[N_NODES_];
__device__ int   g_perm[N_EDGES_];
__device__ int4  g_meta_sorted[N_EDGES_];        // {src, eid, fc_bits, 0}
__device__ float g_rbf_sorted[(size_t)N_EDGES_ * NUM_BASIS_];
__device__ unsigned int g_syncA;

// ---------------------------------------------------------------------------
__device__ __forceinline__ void grid_barrier(unsigned int* ctr, int nblk) {
    __syncthreads();
    if (threadIdx.x == 0) {
        __threadfence();
        unsigned int arrive = atomicAdd(ctr, 1u) + 1u;
        unsigned int target = ((arrive - 1u) / (unsigned)nblk + 1u) * (unsigned)nblk;
        unsigned int v;
        do {
            asm volatile("ld.acquire.gpu.u32 %0, [%1];" : "=r"(v) : "l"(ctr));
        } while (v < target);
    }
    __syncthreads();
}

// ---------------------------------------------------------------------------
// Fused counting sort + sorted-metadata materialization.
// ---------------------------------------------------------------------------
__global__ __launch_bounds__(1024) void sort_kernel(
    const int* __restrict__ edge_index, const float* __restrict__ fcut,
    const float* __restrict__ rbf) {
    const int gsz = gridDim.x * blockDim.x;
    const int gtid = blockIdx.x * blockDim.x + threadIdx.x;

    for (int e = gtid; e < N_EDGES_; e += gsz)
        atomicAdd(&g_count[edge_index[e]], 1);
    grid_barrier(&g_syncA, SORT_BLKS_);

    if (blockIdx.x == 0) {
        __shared__ int s[1024];
        const int C = 30;
        const int t = threadIdx.x;
        const int base = t * C;
        int local[C];
        int sum = 0;
        #pragma unroll
        for (int j = 0; j < C; j++) {
            int i = base + j;
            int v = (i < N_NODES_) ? g_count[i] : 0;
            local[j] = sum;
            sum += v;
        }
        s[t] = sum;
        __syncthreads();
        #pragma unroll
        for (int d = 1; d < 1024; d <<= 1) {
            int x = (t >= d) ? s[t - d] : 0;
            __syncthreads();
            s[t] += x;
            __syncthreads();
        }
        int pre = (t > 0) ? s[t - 1] : 0;
        #pragma unroll
        for (int j = 0; j < C; j++) {
            int i = base + j;
            if (i < N_NODES_) {
                int o = pre + local[j];
                g_offs[i] = o;
                g_cursor[i] = o;
                g_count[i] = 0;
            }
        }
        if (t == 1023) g_offs[N_NODES_] = s[1023];
    }
    grid_barrier(&g_syncA, SORT_BLKS_);

    for (int e = gtid; e < N_EDGES_; e += gsz) {
        int d = edge_index[e];
        int p = atomicAdd(&g_cursor[d], 1);
        g_perm[p] = e;
        g_meta_sorted[p] = make_int4(edge_index[N_EDGES_ + e], e,
                                     __float_as_int(fcut[e]), 0);
    }
    grid_barrier(&g_syncA, SORT_BLKS_);

    for (long long i = gtid; i < (long long)N_EDGES_ * NUM_BASIS_; i += gsz) {
        int p = (int)(i / NUM_BASIS_);
        int k = (int)(i - (long long)p * NUM_BASIS_);
        g_rbf_sorted[i] = rbf[(size_t)g_perm[p] * NUM_BASIS_ + k];
    }
}

// ---------------------------------------------------------------------------
// SGEMM 64x64, 4x4 contiguous microtile
// ---------------------------------------------------------------------------
template <bool DO_SILU>
__global__ __launch_bounds__(256) void sgemm_bias(
    const float* __restrict__ A, const float* __restrict__ B,
    const float* __restrict__ bias, float* __restrict__ C,
    int M, int N, int K) {
    __shared__ __align__(16) float As[16][68];
    __shared__ __align__(16) float Bs[16][64];
    const int bm = blockIdx.y * 64;
    const int bn = blockIdx.x * 64;
    const int tid = threadIdx.x;
    const int tx = tid & 15;
    const int ty = tid >> 4;

    float acc[4][4] = {};

    for (int k0 = 0; k0 < K; k0 += 16) {
        #pragma unroll
        for (int i = 0; i < 4; i++) {
            int idx = tid + 256 * i;
            int m = idx >> 4, k = idx & 15;
            int gm = bm + m;
            As[k][m] = (gm < M) ? A[(size_t)gm * K + k0 + k] : 0.0f;
        }
        #pragma unroll
        for (int i = 0; i < 4; i++) {
            int idx = tid + 256 * i;
            int k = idx >> 6, n = idx & 63;
            Bs[k][n] = B[(size_t)(k0 + k) * N + bn + n];
        }
        __syncthreads();
        #pragma unroll
        for (int k = 0; k < 16; k++) {
            float4 aq = *reinterpret_cast<const float4*>(&As[k][ty * 4]);
            float4 bq = *reinterpret_cast<const float4*>(&Bs[k][tx * 4]);
            float a[4] = {aq.x, aq.y, aq.z, aq.w};
            float b[4] = {bq.x, bq.y, bq.z, bq.w};
            #pragma unroll
            for (int i = 0; i < 4; i++)
                #pragma unroll
                for (int j = 0; j < 4; j++)
                    acc[i][j] = fmaf(a[i], b[j], acc[i][j]);
        }
        __syncthreads();
    }

    float4 bq = *reinterpret_cast<const float4*>(&bias[bn + tx * 4]);
    float bv[4] = {bq.x, bq.y, bq.z, bq.w};
    #pragma unroll
    for (int i = 0; i < 4; i++) {
        int m = bm + ty * 4 + i;
        if (m >= M) continue;
        float4 o;
        float* op = &o.x;
        #pragma unroll
        for (int j = 0; j < 4; j++) {
            float v = acc[i][j] + bv[j];
            if (DO_SILU) v = v / (1.0f + expf(-v));
            op[j] = v;
        }
        *reinterpret_cast<float4*>(&C[(size_t)m * N + bn + tx * 4]) = o;
    }
}

// ---------------------------------------------------------------------------
// Warp-autonomous node kernel: NO __syncthreads in the main loop.
// Warp w of each block owns components [32w, 32w+32); its needed gate irreps
// fit inside the warp, so gates are computed lane-locally and distributed via
// __shfl_sync. All warps iterate the node list independently.
// ---------------------------------------------------------------------------
__device__ __forceinline__ int irrep_of(int k) {
    if (k < 128) return k;
    if (k < 320) return 128 + (k - 128) / 3;
    return 192 + (k - 320) / 5;
}

__global__ __launch_bounds__(576, 1) void node_kernel(
    const float* __restrict__ rsh,
    const float* __restrict__ Wrbf, const float* __restrict__ brbf,
    const float* __restrict__ x_scalar, const float* __restrict__ x_sph,
    float* __restrict__ out_scalar, float* __restrict__ out_sph) {
    const float* __restrict__ so = g_scalar_out;

    const int t = threadIdx.x;
    const int w = t >> 5;
    const int j = t & 31;

    // ---- static lane role computation ----
    const bool sphw = (w < 15);                 // warp does spherical messages
    const int  c0   = w * 32;
    const int  irLo = sphw ? irrep_of(c0) : 0;
    const int  irHi = sphw ? irrep_of(min(c0 + 31, SPH_DIM_ - 1)) : 0;
    const int  nIr  = irHi - irLo + 1;
    const bool wide = (w < 4);                  // nIr == 32: lane does gs+ge

    int colA = -1, colB = -1;
    if (w < 4) {
        colA = irLo + j;                        // gs
        colB = NUM_IRREPS_ + irLo + j;          // ge
    } else if (w < 14) {
        if (j < nIr)           colA = irLo + j;                       // gs
        else if (j < 2 * nIr)  colA = NUM_IRREPS_ + irLo + (j - nIr); // ge
    } else if (w == 14) {
        if (j < nIr)           colA = irLo + j;
        else if (j < 2 * nIr)  colA = NUM_IRREPS_ + irLo + (j - nIr);
        colB = 448 + j;                         // scalar col
    } else {
        colA = t;                               // scalar col (480..575)
    }
    const bool hasA = (colA >= 0);
    const bool hasB = (colB >= 0);
    const int  cA = hasA ? colA : 0;
    const int  cB = hasB ? colB : 0;
    const bool warpHasB = wide || (w == 14);    // warp-uniform

    const int ir   = sphw ? irrep_of(t) : 0;
    const int lsGS = ir - irLo;
    const int lsGE = wide ? (ir - irLo) : (nIr + ir - irLo);

    const bool hasScal = (w == 14) || (w >= 15);
    const int  scol    = (w == 14) ? (colB - 448) : (t - 448);  // out_scalar col

    // weights resident in registers
    float wA[NUM_BASIS_], wB[NUM_BASIS_];
    #pragma unroll
    for (int k = 0; k < NUM_BASIS_; k++) {
        wA[k] = Wrbf[k * HIDDEN_ + cA];
        wB[k] = Wrbf[k * HIDDEN_ + cB];
    }
    const float biasA = brbf[cA];
    const float biasB = brbf[cB];

    for (int n = blockIdx.x; n < N_NODES_; n += gridDim.x) {
        const int off = g_offs[n];
        const int deg = g_offs[n + 1] - off;

        float acc_sph = 0.0f;
        float acc_sc  = 0.0f;

        // depth-1 register pipeline over edges
        int   srcP = 0, eidP = 0;
        float fcP = 0.0f, soAP = 0.0f, soBP = 0.0f, xvP = 0.0f, rvP = 0.0f;
        if (deg > 0) {
            int4 m = __ldg(&g_meta_sorted[off]);
            srcP = m.x; eidP = m.y; fcP = __int_as_float(m.z);
            soAP = hasA ? __ldg(&so[(size_t)srcP * HIDDEN_ + cA]) : 0.0f;
            soBP = hasB ? __ldg(&so[(size_t)srcP * HIDDEN_ + cB]) : 0.0f;
            if (sphw) {
                xvP = __ldg(&x_sph[(size_t)srcP * SPH_DIM_ + t]);
                rvP = __ldcs(&rsh[(size_t)eidP * SPH_DIM_ + t]);
            }
        }

        #pragma unroll 2
        for (int g = 0; g < deg; g++) {
            // consume pipeline regs
            const float fc = fcP, soA = soAP, soB = soBP, xv = xvP, rv = rvP;

            // refill for g+1 (clamped; unused on last iteration)
            {
                int gn = (g + 1 < deg) ? (g + 1) : g;
                int4 m = __ldg(&g_meta_sorted[off + gn]);
                srcP = m.x; eidP = m.y; fcP = __int_as_float(m.z);
                soAP = hasA ? __ldg(&so[(size_t)srcP * HIDDEN_ + cA]) : 0.0f;
                soBP = hasB ? __ldg(&so[(size_t)srcP * HIDDEN_ + cB]) : 0.0f;
                if (sphw) {
                    xvP = __ldg(&x_sph[(size_t)srcP * SPH_DIM_ + t]);
                    rvP = __ldcs(&rsh[(size_t)eidP * SPH_DIM_ + t]);
                }
            }

            // rbf for this edge: 5 uniform float4 loads (sorted, sequential)
            const float4* rq = reinterpret_cast<const float4*>(
                g_rbf_sorted + (size_t)(off + g) * NUM_BASIS_);
            float4 q0 = __ldg(rq), q1 = __ldg(rq + 1), q2 = __ldg(rq + 2),
                   q3 = __ldg(rq + 3), q4 = __ldg(rq + 4);
            const float r[NUM_BASIS_] = {
                q0.x, q0.y, q0.z, q0.w, q1.x, q1.y, q1.z, q1.w,
                q2.x, q2.y, q2.z, q2.w, q3.x, q3.y, q3.z, q3.w,
                q4.x, q4.y, q4.z, q4.w };

            float dA = biasA;
            #pragma unroll
            for (int k = 0; k < NUM_BASIS_; k++) dA = fmaf(r[k], wA[k], dA);
            float resA = soA * dA * fc;

            float resB = 0.0f;
            if (warpHasB) {                      // warp-uniform branch
                float dB = biasB;
                #pragma unroll
                for (int k = 0; k < NUM_BASIS_; k++) dB = fmaf(r[k], wB[k], dB);
                resB = soB * dB * fc;
            }

            if (sphw) {
                float gsv = __shfl_sync(0xffffffffu, resA, lsGS);
                float gev = wide ? __shfl_sync(0xffffffffu, resB, lsGE)
                                 : __shfl_sync(0xffffffffu, resA, lsGE);
                acc_sph = fmaf(xv, gsv, acc_sph);
                acc_sph = fmaf(rv, gev, acc_sph);
            }
            if (hasScal) acc_sc += (w == 14) ? resB : resA;
        }

        // residual + single write (covers deg==0 too)
        if (sphw)
            out_sph[(size_t)n * SPH_DIM_ + t] =
                x_sph[(size_t)n * SPH_DIM_ + t] + acc_sph;
        if (hasScal)
            out_scalar[(size_t)n * NODE_DIM_ + scol] =
                x_scalar[(size_t)n * NODE_DIM_ + scol] + acc_sc;
    }
}

// ---------------------------------------------------------------------------
extern "C" void kernel_launch(void* const* d_in, const int* in_sizes, int n_in,
                              void* d_out, int out_size) {
    const float* x_scalar = (const float*)d_in[0];
    const float* x_sph    = (const float*)d_in[1];
    const float* rbf      = (const float*)d_in[2];
    const float* fcut     = (const float*)d_in[3];
    const float* rsh      = (const float*)d_in[4];
    const int*   eidx     = (const int*)d_in[5];
    const float* W1       = (const float*)d_in[6];
    const float* b1       = (const float*)d_in[7];
    const float* W2       = (const float*)d_in[8];
    const float* b2       = (const float*)d_in[9];
    const float* Wrbf     = (const float*)d_in[10];
    const float* brbf     = (const float*)d_in[11];

    float* out        = (float*)d_out;
    float* out_scalar = out;
    float* out_sph    = out + (size_t)N_NODES_ * NODE_DIM_;

    float* hidden = nullptr;
    float* so     = nullptr;
    cudaGetSymbolAddress((void**)&hidden, g_hidden);
    cudaGetSymbolAddress((void**)&so, g_scalar_out);

    sort_kernel<<<SORT_BLKS_, 1024>>>(eidx, fcut, rbf);                      // 0
    {
        dim3 grid(NODE_DIM_ / 64, (N_NODES_ + 63) / 64);
        sgemm_bias<true><<<grid, 256>>>(x_scalar, W1, b1, hidden,
                                        N_NODES_, NODE_DIM_, NODE_DIM_);     // 1
    }
    {
        dim3 grid(HIDDEN_ / 64, (N_NODES_ + 63) / 64);
        sgemm_bias<false><<<grid, 256>>>(hidden, W2, b2, so,
                                         N_NODES_, HIDDEN_, NODE_DIM_);      // 2
    }
    node_kernel<<<148, 576>>>(rsh, Wrbf, brbf,
                              x_scalar, x_sph, out_scalar, out_sph);         // 3
}

// round 15
// speedup vs baseline: 1.9652x; 1.9652x over previous
#include <cuda_runtime.h>
#include <cstdint>
#include <math.h>

#define NODE_DIM_   128
#define NUM_IRREPS_ 224
#define SPH_DIM_    480
#define HIDDEN_     576
#define NUM_BASIS_  20
#define N_NODES_    30000
#define N_EDGES_    480000
#define EPB_        8
#define MAXD_       32
#define SORT_BLKS_  148

// Scratch (device globals)
__device__ float g_hidden[(size_t)N_NODES_ * NODE_DIM_];
__device__ float g_scalar_out[(size_t)N_NODES_ * HIDDEN_];
__device__ int   g_count[N_NODES_];
__device__ int   g_offs[N_NODES_ + 1];
__device__ int   g_cursor[N_NODES_];
__device__ int   g_perm[N_EDGES_];
__device__ int   g_src_sorted[N_EDGES_];
__device__ float g_fc_sorted[N_EDGES_];
__device__ unsigned int g_syncA;

// ---------------------------------------------------------------------------
__device__ __forceinline__ void grid_barrier(unsigned int* ctr, int nblk) {
    __syncthreads();
    if (threadIdx.x == 0) {
        __threadfence();
        unsigned int arrive = atomicAdd(ctr, 1u) + 1u;
        unsigned int target = ((arrive - 1u) / (unsigned)nblk + 1u) * (unsigned)nblk;
        unsigned int v;
        do {
            asm volatile("ld.acquire.gpu.u32 %0, [%1];" : "=r"(v) : "l"(ctr));
        } while (v < target);
    }
    __syncthreads();
}

// ---------------------------------------------------------------------------
// Fused counting sort (+ sorted src/fc arrays; no heavy rbf materialization)
// ---------------------------------------------------------------------------
__global__ __launch_bounds__(1024) void sort_kernel(
    const int* __restrict__ edge_index, const float* __restrict__ fcut) {
    const int gsz = gridDim.x * blockDim.x;
    const int gtid = blockIdx.x * blockDim.x + threadIdx.x;

    for (int e = gtid; e < N_EDGES_; e += gsz)
        atomicAdd(&g_count[edge_index[e]], 1);
    grid_barrier(&g_syncA, SORT_BLKS_);

    if (blockIdx.x == 0) {
        __shared__ int s[1024];
        const int C = 30;
        const int t = threadIdx.x;
        const int base = t * C;
        int local[C];
        int sum = 0;
        #pragma unroll
        for (int j = 0; j < C; j++) {
            int i = base + j;
            int v = (i < N_NODES_) ? g_count[i] : 0;
            local[j] = sum;
            sum += v;
        }
        s[t] = sum;
        __syncthreads();
        #pragma unroll
        for (int d = 1; d < 1024; d <<= 1) {
            int x = (t >= d) ? s[t - d] : 0;
            __syncthreads();
            s[t] += x;
            __syncthreads();
        }
        int pre = (t > 0) ? s[t - 1] : 0;
        #pragma unroll
        for (int j = 0; j < C; j++) {
            int i = base + j;
            if (i < N_NODES_) {
                int o = pre + local[j];
                g_offs[i] = o;
                g_cursor[i] = o;
                g_count[i] = 0;
            }
        }
        if (t == 1023) g_offs[N_NODES_] = s[1023];
    }
    grid_barrier(&g_syncA, SORT_BLKS_);

    for (int e = gtid; e < N_EDGES_; e += gsz) {
        int d = edge_index[e];
        int p = atomicAdd(&g_cursor[d], 1);
        g_perm[p] = e;
        g_src_sorted[p] = edge_index[N_EDGES_ + e];
        g_fc_sorted[p] = fcut[e];
    }
}

// ---------------------------------------------------------------------------
// SGEMM 64x64, 4x4 contiguous microtile
// ---------------------------------------------------------------------------
template <bool DO_SILU>
__global__ __launch_bounds__(256) void sgemm_bias(
    const float* __restrict__ A, const float* __restrict__ B,
    const float* __restrict__ bias, float* __restrict__ C,
    int M, int N, int K) {
    __shared__ __align__(16) float As[16][68];
    __shared__ __align__(16) float Bs[16][64];
    const int bm = blockIdx.y * 64;
    const int bn = blockIdx.x * 64;
    const int tid = threadIdx.x;
    const int tx = tid & 15;
    const int ty = tid >> 4;

    float acc[4][4] = {};

    for (int k0 = 0; k0 < K; k0 += 16) {
        #pragma unroll
        for (int i = 0; i < 4; i++) {
            int idx = tid + 256 * i;
            int m = idx >> 4, k = idx & 15;
            int gm = bm + m;
            As[k][m] = (gm < M) ? A[(size_t)gm * K + k0 + k] : 0.0f;
        }
        #pragma unroll
        for (int i = 0; i < 4; i++) {
            int idx = tid + 256 * i;
            int k = idx >> 6, n = idx & 63;
            Bs[k][n] = B[(size_t)(k0 + k) * N + bn + n];
        }
        __syncthreads();
        #pragma unroll
        for (int k = 0; k < 16; k++) {
            float4 aq = *reinterpret_cast<const float4*>(&As[k][ty * 4]);
            float4 bq = *reinterpret_cast<const float4*>(&Bs[k][tx * 4]);
            float a[4] = {aq.x, aq.y, aq.z, aq.w};
            float b[4] = {bq.x, bq.y, bq.z, bq.w};
            #pragma unroll
            for (int i = 0; i < 4; i++)
                #pragma unroll
                for (int j = 0; j < 4; j++)
                    acc[i][j] = fmaf(a[i], b[j], acc[i][j]);
        }
        __syncthreads();
    }

    float4 bq = *reinterpret_cast<const float4*>(&bias[bn + tx * 4]);
    float bv[4] = {bq.x, bq.y, bq.z, bq.w};
    #pragma unroll
    for (int i = 0; i < 4; i++) {
        int m = bm + ty * 4 + i;
        if (m >= M) continue;
        float4 o;
        float* op = &o.x;
        #pragma unroll
        for (int j = 0; j < 4; j++) {
            float v = acc[i][j] + bv[j];
            if (DO_SILU) v = v / (1.0f + expf(-v));
            op[j] = v;
        }
        *reinterpret_cast<float4*>(&C[(size_t)m * N + bn + tx * 4]) = o;
    }
}

// ---------------------------------------------------------------------------
// Spherical kernel P: 480 threads, 2 blocks/SM (30 warps).
// R8-proven batch structure; gate cols t<448, messages all t.
// ---------------------------------------------------------------------------
__device__ __forceinline__ int irrep_of(int k) {
    if (k < 128) return k;
    if (k < 320) return 128 + (k - 128) / 3;
    return 192 + (k - 320) / 5;
}

__global__ __launch_bounds__(480, 2) void sph_kernel(
    const float* __restrict__ rbf, const float* __restrict__ rsh,
    const float* __restrict__ Wrbf, const float* __restrict__ brbf,
    const float* __restrict__ x_sph, float* __restrict__ out_sph) {
    const float* __restrict__ so = g_scalar_out;

    __shared__ __align__(16) float rbf_s[MAXD_][24];
    __shared__ int   eid_s[MAXD_];
    __shared__ int   src_s[MAXD_];
    __shared__ float fc_s[MAXD_];
    __shared__ float gate_s[2][EPB_][2 * NUM_IRREPS_];

    const int t = threadIdx.x;
    const bool gcol = (t < 2 * NUM_IRREPS_);
    const int wcol = gcol ? t : 0;

    float w[NUM_BASIS_];
    #pragma unroll
    for (int k = 0; k < NUM_BASIS_; k++) w[k] = Wrbf[k * HIDDEN_ + wcol];
    const float bb = brbf[wcol];
    const int ir = irrep_of(t);

    for (int n = blockIdx.x; n < N_NODES_; n += gridDim.x) {
        const int off = g_offs[n];
        const int deg = g_offs[n + 1] - off;

        float acc = 0.0f;

        for (int c0 = 0; c0 < deg; c0 += MAXD_) {
            const int cnt = min(MAXD_, deg - c0);
            const int bp = off + c0;

            __syncthreads();   // prev chunk smem consumed

            if (t < MAXD_) {
                int jj = (t < cnt) ? t : cnt - 1;
                eid_s[t] = __ldg(&g_perm[bp + jj]);
                src_s[t] = __ldg(&g_src_sorted[bp + jj]);
                fc_s[t]  = (t < cnt) ? __ldg(&g_fc_sorted[bp + t]) : 0.0f;
            }
            for (int i = t; i < cnt * NUM_BASIS_; i += 480) {
                int e = i / NUM_BASIS_, k = i - e * NUM_BASIS_;
                int eid = __ldg(&g_perm[bp + e]);     // L1 broadcast
                rbf_s[e][k] = __ldg(&rbf[(size_t)eid * NUM_BASIS_ + k]);
            }
            __syncthreads();

            const int nb = (cnt + EPB_ - 1) / EPB_;
            for (int b = 0; b < nb; b++) {
                const int base = b * EPB_;

                // all gathers issued up front (8-deep MLP each stream)
                float s[EPB_], xv[EPB_], rv[EPB_];
                #pragma unroll
                for (int e = 0; e < EPB_; e++) {
                    int sp = src_s[base + e];
                    s[e]  = gcol ? __ldg(&so[(size_t)sp * HIDDEN_ + t]) : 0.0f;
                    xv[e] = __ldg(&x_sph[(size_t)sp * SPH_DIM_ + t]);
                    rv[e] = __ldcs(&rsh[(size_t)eid_s[base + e] * SPH_DIM_ + t]);
                }

                if (gcol) {
                    float a[EPB_];
                    #pragma unroll
                    for (int e = 0; e < EPB_; e++) {
                        const float4* rp =
                            reinterpret_cast<const float4*>(&rbf_s[base + e][0]);
                        float4 q0 = rp[0], q1 = rp[1], q2 = rp[2], q3 = rp[3],
                               q4 = rp[4];
                        float v = bb;
                        v = fmaf(q0.x, w[0],  v); v = fmaf(q0.y, w[1],  v);
                        v = fmaf(q0.z, w[2],  v); v = fmaf(q0.w, w[3],  v);
                        v = fmaf(q1.x, w[4],  v); v = fmaf(q1.y, w[5],  v);
                        v = fmaf(q1.z, w[6],  v); v = fmaf(q1.w, w[7],  v);
                        v = fmaf(q2.x, w[8],  v); v = fmaf(q2.y, w[9],  v);
                        v = fmaf(q2.z, w[10], v); v = fmaf(q2.w, w[11], v);
                        v = fmaf(q3.x, w[12], v); v = fmaf(q3.y, w[13], v);
                        v = fmaf(q3.z, w[14], v); v = fmaf(q3.w, w[15], v);
                        v = fmaf(q4.x, w[16], v); v = fmaf(q4.y, w[17], v);
                        v = fmaf(q4.z, w[18], v); v = fmaf(q4.w, w[19], v);
                        a[e] = v;
                    }
                    #pragma unroll
                    for (int e = 0; e < EPB_; e++)
                        gate_s[b & 1][e][t] = s[e] * (a[e] * fc_s[base + e]);
                }
                __syncthreads();   // gates ready; gathers land during wait

                #pragma unroll
                for (int e = 0; e < EPB_; e++) {
                    const float* ge = gate_s[b & 1][e];
                    acc = fmaf(xv[e], ge[ir], acc);
                    acc = fmaf(rv[e], ge[NUM_IRREPS_ + ir], acc);
                }
            }
        }

        out_sph[(size_t)n * SPH_DIM_ + t] =
            x_sph[(size_t)n * SPH_DIM_ + t] + acc;
    }
}

// ---------------------------------------------------------------------------
// Scalar kernel S: new_scalar. One block per node, 128 threads (col each).
// rbf via uniform broadcast float4 loads; gather coalesced. No barriers.
// ---------------------------------------------------------------------------
__global__ __launch_bounds__(128) void scalar_kernel(
    const float* __restrict__ rbf,
    const float* __restrict__ Wrbf, const float* __restrict__ brbf,
    const float* __restrict__ x_scalar, float* __restrict__ out_scalar) {
    const float* __restrict__ so = g_scalar_out;

    const int t = threadIdx.x;
    const int col = 2 * NUM_IRREPS_ + t;      // 448 + t
    const int n = blockIdx.x;

    float w[NUM_BASIS_];
    #pragma unroll
    for (int k = 0; k < NUM_BASIS_; k++) w[k] = __ldg(&Wrbf[k * HIDDEN_ + col]);
    const float bb = __ldg(&brbf[col]);

    const int off = g_offs[n];
    const int deg = g_offs[n + 1] - off;

    float acc = 0.0f;
    for (int g = 0; g < deg; g++) {
        int eid = __ldg(&g_perm[off + g]);
        int src = __ldg(&g_src_sorted[off + g]);
        float fc = __ldg(&g_fc_sorted[off + g]);

        const float4* rq = reinterpret_cast<const float4*>(
            rbf + (size_t)eid * NUM_BASIS_);
        float4 q0 = __ldg(rq), q1 = __ldg(rq + 1), q2 = __ldg(rq + 2),
               q3 = __ldg(rq + 3), q4 = __ldg(rq + 4);

        float sv = __ldg(&so[(size_t)src * HIDDEN_ + col]);

        float v = bb;
        v = fmaf(q0.x, w[0],  v); v = fmaf(q0.y, w[1],  v);
        v = fmaf(q0.z, w[2],  v); v = fmaf(q0.w, w[3],  v);
        v = fmaf(q1.x, w[4],  v); v = fmaf(q1.y, w[5],  v);
        v = fmaf(q1.z, w[6],  v); v = fmaf(q1.w, w[7],  v);
        v = fmaf(q2.x, w[8],  v); v = fmaf(q2.y, w[9],  v);
        v = fmaf(q2.z, w[10], v); v = fmaf(q2.w, w[11], v);
        v = fmaf(q3.x, w[12], v); v = fmaf(q3.y, w[13], v);
        v = fmaf(q3.z, w[14], v); v = fmaf(q3.w, w[15], v);
        v = fmaf(q4.x, w[16], v); v = fmaf(q4.y, w[17], v);
        v = fmaf(q4.z, w[18], v); v = fmaf(q4.w, w[19], v);

        acc = fmaf(sv, v * fc, acc);
    }

    out_scalar[(size_t)n * NODE_DIM_ + t] =
        x_scalar[(size_t)n * NODE_DIM_ + t] + acc;
}

// ---------------------------------------------------------------------------
extern "C" void kernel_launch(void* const* d_in, const int* in_sizes, int n_in,
                              void* d_out, int out_size) {
    const float* x_scalar = (const float*)d_in[0];
    const float* x_sph    = (const float*)d_in[1];
    const float* rbf      = (const float*)d_in[2];
    const float* fcut     = (const float*)d_in[3];
    const float* rsh      = (const float*)d_in[4];
    const int*   eidx     = (const int*)d_in[5];
    const float* W1       = (const float*)d_in[6];
    const float* b1       = (const float*)d_in[7];
    const float* W2       = (const float*)d_in[8];
    const float* b2       = (const float*)d_in[9];
    const float* Wrbf     = (const float*)d_in[10];
    const float* brbf     = (const float*)d_in[11];

    float* out        = (float*)d_out;
    float* out_scalar = out;
    float* out_sph    = out + (size_t)N_NODES_ * NODE_DIM_;

    float* hidden = nullptr;
    float* so     = nullptr;
    cudaGetSymbolAddress((void**)&hidden, g_hidden);
    cudaGetSymbolAddress((void**)&so, g_scalar_out);

    sort_kernel<<<SORT_BLKS_, 1024>>>(eidx, fcut);                           // 0
    {
        dim3 grid(NODE_DIM_ / 64, (N_NODES_ + 63) / 64);
        sgemm_bias<true><<<grid, 256>>>(x_scalar, W1, b1, hidden,
                                        N_NODES_, NODE_DIM_, NODE_DIM_);     // 1
    }
    {
        dim3 grid(HIDDEN_ / 64, (N_NODES_ + 63) / 64);
        sgemm_bias<false><<<grid, 256>>>(hidden, W2, b2, so,
                                         N_NODES_, HIDDEN_, NODE_DIM_);      // 2
    }
    sph_kernel<<<296, 480>>>(rbf, rsh, Wrbf, brbf, x_sph, out_sph);          // 3
    scalar_kernel<<<N_NODES_, 128>>>(rbf, Wrbf, brbf, x_scalar, out_scalar); // 4
}